// round 15
// baseline (speedup 1.0000x reference)
#include <cuda_runtime.h>
#include <cuda_bf16.h>
#include <mma.h>
#include <math.h>
#include <stdint.h>

using namespace nvcuda;

typedef unsigned long long u64;
typedef unsigned int u32;

#define P_PROP 1024
#define NCLS   80
#define NDET   (P_PROP * NCLS)   // 81920
#define KNMS   2048
#define FEAT   12544             // 256*7*7
#define CLIN   1024
#define NHEAD  512               // packed cls(128) + reg(384)
#define BBOX_CLIP 4.135166556742356f

// ------------------------- scratch (device globals; no runtime alloc) ------
__device__ __nv_bfloat16 g_xh [P_PROP * FEAT];
__device__ __nv_bfloat16 g_xl [P_PROP * FEAT];
__device__ __nv_bfloat16 g_w0h[CLIN * FEAT];
__device__ __nv_bfloat16 g_w0l[CLIN * FEAT];
__device__ __nv_bfloat16 g_w1h[CLIN * CLIN];
__device__ __nv_bfloat16 g_w1l[CLIN * CLIN];
__device__ __nv_bfloat16 g_wHh[NHEAD * CLIN];
__device__ __nv_bfloat16 g_wHl[NHEAD * CLIN];
__device__ float  g_part[4 * P_PROP * CLIN];     // split-K partials
__device__ __nv_bfloat16 g_h1h[P_PROP * CLIN];
__device__ __nv_bfloat16 g_h1l[P_PROP * CLIN];
__device__ __nv_bfloat16 g_h2h[P_PROP * CLIN];
__device__ __nv_bfloat16 g_h2l[P_PROP * CLIN];
__device__ float  g_headp[P_PROP * NHEAD];       // raw head out (no bias)
__device__ float  g_scr [P_PROP * NCLS];
__device__ float4 g_boxes[NDET];
__device__ u64    g_keysA[NDET];
__device__ u64    g_keysB[NDET / 2 + 4096];
__device__ float4 g_bk  [KNMS];
__device__ float4 g_ob  [KNMS];
__device__ float  g_sk  [KNMS];
__device__ int    g_ck  [KNMS];
__device__ int    g_imk [KNMS];
__device__ unsigned char g_vk  [KNMS];
__device__ unsigned char g_keep[KNMS];
__device__ u64    g_mask[KNMS * 32];

__device__ __forceinline__ unsigned short bfbits(float x) {
    __nv_bfloat16 b = __float2bfloat16(x);
    return *(unsigned short*)&b;
}

// --------------------------------- RoIAlign --------------------------------
__global__ __launch_bounds__(256) void roi_align_kernel(
    const float* __restrict__ props, const int* __restrict__ imidx,
    const float* __restrict__ f0, const float* __restrict__ f1,
    const float* __restrict__ f2, const float* __restrict__ f3)
{
    const int p  = blockIdx.x / 7;
    const int oy = blockIdx.x % 7;

    __shared__ int   s_xc[28];
    __shared__ float s_xw[28];
    __shared__ int   s_yr[4];
    __shared__ float s_yw[4];
    __shared__ int   s_l, s_im, s_H, s_W;

    if (threadIdx.x < 32) {
        float4 pr = ((const float4*)props)[p];
        float w = pr.z - pr.x, h = pr.w - pr.y;
        float t = sqrtf(w * h) / 224.0f + 1e-8f;
        float lv = floorf(4.0f + log2f(t));
        int l = (int)fminf(fmaxf(lv, 2.0f), 5.0f) - 2;
        int H = 160 >> l, W = 160 >> l;
        float inv = 1.0f / (float)(4 << l);
        float x1 = pr.x * inv - 0.5f, x2 = pr.z * inv - 0.5f;
        float y1 = pr.y * inv - 0.5f, y2 = pr.w * inv - 0.5f;
        float bw = (x2 - x1) / 7.0f, bh = (y2 - y1) / 7.0f;
        int lane = threadIdx.x;
        if (lane < 28) {
            int j = lane >> 1;
            float g  = ((float)j + 0.5f) * 0.5f;
            float xs = x1 + bw * g;
            float vx = (xs > -1.0f && xs < (float)W) ? 1.0f : 0.0f;
            float v  = fminf(fmaxf(xs, 0.0f), (float)W - 1.0f);
            float lo = floorf(v);
            int loi = (int)lo;
            int hii = min(loi + 1, W - 1);
            float fx = v - lo;
            s_xc[lane] = (lane & 1) ? hii : loi;
            s_xw[lane] = (lane & 1) ? (fx * vx) : ((1.0f - fx) * vx);
        }
        if (lane < 4) {
            int q = lane >> 1;
            int sy = oy * 2 + q;
            float g  = ((float)sy + 0.5f) * 0.5f;
            float ys = y1 + bh * g;
            float vy = (ys > -1.0f && ys < (float)H) ? 1.0f : 0.0f;
            float v  = fminf(fmaxf(ys, 0.0f), (float)H - 1.0f);
            float lo = floorf(v);
            int loi = (int)lo;
            int hii = min(loi + 1, H - 1);
            float fy = v - lo;
            s_yr[lane] = (lane & 1) ? hii : loi;
            s_yw[lane] = (lane & 1) ? (fy * vy) : ((1.0f - fy) * vy);
        }
        if (lane == 0) { s_l = l; s_im = imidx[p]; s_H = H; s_W = W; }
    }
    __syncthreads();

    const int l = s_l, H = s_H, W = s_W, im = s_im;
    const float* fm = (l == 0) ? f0 : (l == 1) ? f1 : (l == 2) ? f2 : f3;
    const float* base_im = fm + (size_t)im * 256 * H * W;

    const int warp = threadIdx.x >> 5;
    const int lane = threadIdx.x & 31;
    const float xw = (lane < 28) ? s_xw[lane] : 0.0f;
    const int   xc = (lane < 28) ? s_xc[lane] : 0;
    const int r0 = s_yr[0], r1 = s_yr[1], r2 = s_yr[2], r3 = s_yr[3];
    const float w0 = s_yw[0], w1 = s_yw[1], w2 = s_yw[2], w3 = s_yw[3];

    for (int c = warp; c < 256; c += 8) {
        const float* bc = base_im + (size_t)c * H * W;
        float acc = w0 * bc[r0 * W + xc]
                  + w1 * bc[r1 * W + xc]
                  + w2 * bc[r2 * W + xc]
                  + w3 * bc[r3 * W + xc];
        float m = acc * xw;
        m += __shfl_xor_sync(0xffffffffu, m, 1);
        m += __shfl_xor_sync(0xffffffffu, m, 2);
        if (lane < 28 && (lane & 3) == 0) {
            float val = m * 0.25f;
            size_t off = (size_t)p * FEAT + c * 49 + oy * 7 + (lane >> 2);
            __nv_bfloat16 hi = __float2bfloat16(val);
            g_xh[off] = hi;
            g_xl[off] = __float2bfloat16(val - __bfloat162float(hi));
        }
    }
}

// ------------- fp32 -> bf16 hi/lo split (weights, row-pad, x4 vec) ---------
__global__ __launch_bounds__(256) void split_pad_kernel(
    const float* __restrict__ src, __nv_bfloat16* __restrict__ hi,
    __nv_bfloat16* __restrict__ lo, int rows, int K, int prows)
{
    int i4 = blockIdx.x * 256 + threadIdx.x;
    int total4 = (prows * K) >> 2;
    if (i4 >= total4) return;
    int i = i4 << 2;
    int r = i / K;
    float4 x = make_float4(0.f, 0.f, 0.f, 0.f);
    if (r < rows) x = *(const float4*)(src + i);
    ushort4 h4, l4;
    h4.x = bfbits(x.x); l4.x = bfbits(x.x - __bfloat162float(__float2bfloat16(x.x)));
    h4.y = bfbits(x.y); l4.y = bfbits(x.y - __bfloat162float(__float2bfloat16(x.y)));
    h4.z = bfbits(x.z); l4.z = bfbits(x.z - __bfloat162float(__float2bfloat16(x.z)));
    h4.w = bfbits(x.w); l4.w = bfbits(x.w - __bfloat162float(__float2bfloat16(x.w)));
    *(ushort4*)((unsigned short*)hi + i) = h4;
    *(ushort4*)((unsigned short*)lo + i) = l4;
}

// ---------- partial reduce (cnt buffers) + bias + relu + bf16 split --------
__global__ __launch_bounds__(256) void reduce_split_kernel(
    const float* __restrict__ P, const float* __restrict__ bias,
    __nv_bfloat16* __restrict__ hi, __nv_bfloat16* __restrict__ lo, int cnt)
{
    int i4 = blockIdx.x * 256 + threadIdx.x;
    if (i4 >= (P_PROP * CLIN) >> 2) return;
    int i = i4 << 2;
    float4 a = *(const float4*)(P + i);
    for (int q = 1; q < cnt; q++) {
        float4 b = *(const float4*)(P + (size_t)q * P_PROP * CLIN + i);
        a.x += b.x; a.y += b.y; a.z += b.z; a.w += b.w;
    }
    float4 bb = *(const float4*)(bias + (i & (CLIN - 1)));
    float v0 = fmaxf(a.x + bb.x, 0.f);
    float v1 = fmaxf(a.y + bb.y, 0.f);
    float v2 = fmaxf(a.z + bb.z, 0.f);
    float v3 = fmaxf(a.w + bb.w, 0.f);
    ushort4 h4, l4;
    h4.x = bfbits(v0); l4.x = bfbits(v0 - __bfloat162float(__float2bfloat16(v0)));
    h4.y = bfbits(v1); l4.y = bfbits(v1 - __bfloat162float(__float2bfloat16(v1)));
    h4.z = bfbits(v2); l4.z = bfbits(v2 - __bfloat162float(__float2bfloat16(v2)));
    h4.w = bfbits(v3); l4.w = bfbits(v3 - __bfloat162float(__float2bfloat16(v3)));
    *(ushort4*)((unsigned short*)hi + i) = h4;
    *(ushort4*)((unsigned short*)lo + i) = l4;
}

// ------------------- head partial reduce (cnt buffers, raw) ----------------
__global__ __launch_bounds__(256) void head_reduce_kernel(const float* __restrict__ P, int cnt)
{
    int i4 = blockIdx.x * 256 + threadIdx.x;
    if (i4 >= (P_PROP * NHEAD) >> 2) return;
    int i = i4 << 2;
    float4 a = *(const float4*)(P + i);
    for (int q = 1; q < cnt; q++) {
        float4 b = *(const float4*)(P + (size_t)q * P_PROP * NHEAD + i);
        a.x += b.x; a.y += b.y; a.z += b.z; a.w += b.w;
    }
    *(float4*)(g_headp + i) = a;
}

// -------------------------- wmma split-bf16 GEMM (R12-proven) --------------
// C[m][n] = sum_k A[m][k]*B[n][k] via (AhBh + AhBl + AlBh), fp32 accumulate.
// 128x128 CTA tile, 512 threads, 16 warps (each 32x32), BK=32,
// 4-stage smem ring, ONE __syncthreads per chunk, 2-chunk prefetch distance.
// blockIdx.z selects K-part (offset z*K in k, z*partStride in out).
#define LDT 40                       // smem row pitch (elements)
#define MATE (128 * LDT)             // elements per matrix tile (5120)
#define STAGEE (4 * MATE)            // elements per stage (20480)
#define NSTAGE 4
#define SMEM_GEMM (NSTAGE * STAGEE * 2)   // bytes (163840)

__global__ __launch_bounds__(512) void gemm_wmma_kernel(
    const __nv_bfloat16* __restrict__ Ah, const __nv_bfloat16* __restrict__ Al,
    const __nv_bfloat16* __restrict__ Bh, const __nv_bfloat16* __restrict__ Bl,
    float* __restrict__ C, int N, int K, int ldk, int partStride)
{
    extern __shared__ __align__(32) __nv_bfloat16 smem[];
    const int tid = threadIdx.x;
    const int wid = tid >> 5;
    const int wm = wid & 3;           // rows wm*32
    const int wn = wid >> 2;          // cols wn*32
    const size_t arow = (size_t)blockIdx.y * 128;
    const size_t brow = (size_t)blockIdx.x * 128;
    const size_t koff = (size_t)blockIdx.z * K;

    const int row = tid >> 2;         // 0..127
    const int seg = tid & 3;          // 0..3

    wmma::fragment<wmma::accumulator, 16, 16, 16, float> cf[2][2];
    #pragma unroll
    for (int i = 0; i < 2; i++)
        #pragma unroll
        for (int j = 0; j < 2; j++) wmma::fill_fragment(cf[i][j], 0.0f);

    uint4 rAh, rAl, rBh, rBl;
    auto reg_load = [&](size_t kpos) {
        size_t ga = (arow + row) * (size_t)ldk + kpos + seg * 8;
        size_t gb = (brow + row) * (size_t)ldk + kpos + seg * 8;
        rAh = *(const uint4*)(Ah + ga);
        rAl = *(const uint4*)(Al + ga);
        rBh = *(const uint4*)(Bh + gb);
        rBl = *(const uint4*)(Bl + gb);
    };
    auto smem_store = [&](int st) {
        __nv_bfloat16* base = smem + st * STAGEE;
        int so = row * LDT + seg * 8;
        *(uint4*)(base + so)            = rAh;
        *(uint4*)(base + MATE + so)     = rAl;
        *(uint4*)(base + 2 * MATE + so) = rBh;
        *(uint4*)(base + 3 * MATE + so) = rBl;
    };

    const int nch = K / 32;
    // prologue: fill stages 0 and 1
    reg_load(koff);
    smem_store(0);
    if (nch > 1) {
        reg_load(koff + 32);
        smem_store(1);
    }
    __syncthreads();

    for (int ch = 0; ch < nch; ch++) {
        const bool pf = (ch + 2 < nch);
        if (pf) reg_load(koff + (size_t)(ch + 2) * 32);
        {
            const __nv_bfloat16* base = smem + (ch & (NSTAGE - 1)) * STAGEE;
            const __nv_bfloat16* sAh = base;
            const __nv_bfloat16* sAl = base + MATE;
            const __nv_bfloat16* sBh = base + 2 * MATE;
            const __nv_bfloat16* sBl = base + 3 * MATE;
            #pragma unroll
            for (int ks = 0; ks < 2; ks++) {
                wmma::fragment<wmma::matrix_a, 16, 16, 16, __nv_bfloat16, wmma::row_major> ah[2], al[2];
                wmma::fragment<wmma::matrix_b, 16, 16, 16, __nv_bfloat16, wmma::col_major> bh[2], bl[2];
                #pragma unroll
                for (int i = 0; i < 2; i++) {
                    wmma::load_matrix_sync(ah[i], sAh + (wm * 32 + i * 16) * LDT + ks * 16, LDT);
                    wmma::load_matrix_sync(al[i], sAl + (wm * 32 + i * 16) * LDT + ks * 16, LDT);
                }
                #pragma unroll
                for (int j = 0; j < 2; j++) {
                    wmma::load_matrix_sync(bh[j], sBh + (wn * 32 + j * 16) * LDT + ks * 16, LDT);
                    wmma::load_matrix_sync(bl[j], sBl + (wn * 32 + j * 16) * LDT + ks * 16, LDT);
                }
                #pragma unroll
                for (int i = 0; i < 2; i++)
                    #pragma unroll
                    for (int j = 0; j < 2; j++) {
                        wmma::mma_sync(cf[i][j], ah[i], bh[j], cf[i][j]);
                        wmma::mma_sync(cf[i][j], ah[i], bl[j], cf[i][j]);
                        wmma::mma_sync(cf[i][j], al[i], bh[j], cf[i][j]);
                    }
            }
        }
        __syncthreads();
        if (pf) smem_store((ch + 2) & (NSTAGE - 1));
    }

    float* Cout = C + (size_t)blockIdx.z * partStride;
    #pragma unroll
    for (int i = 0; i < 2; i++)
        #pragma unroll
        for (int j = 0; j < 2; j++)
            wmma::store_matrix_sync(
                Cout + (arow + wm * 32 + i * 16) * (size_t)N + brow + wn * 32 + j * 16,
                cf[i][j], N, wmma::mem_row_major);
}

// --------------------------------- softmax ---------------------------------
__global__ __launch_bounds__(128) void softmax_kernel(const float* __restrict__ cls_b)
{
    const int p = blockIdx.x, t = threadIdx.x;
    __shared__ float red[128];
    float v = (t < 81) ? (g_headp[p * NHEAD + t] + cls_b[t]) : -3.0e38f;
    red[t] = v; __syncthreads();
    for (int s = 64; s > 0; s >>= 1) {
        if (t < s) red[t] = fmaxf(red[t], red[t + s]);
        __syncthreads();
    }
    float mx = red[0]; __syncthreads();
    float e = (t < 81) ? expf(v - mx) : 0.0f;
    red[t] = e; __syncthreads();
    for (int s = 64; s > 0; s >>= 1) {
        if (t < s) red[t] += red[t + s];
        __syncthreads();
    }
    float total = red[0];
    if (t < 80) g_scr[p * NCLS + t] = e / total;
}

// ------------------------------- box decode --------------------------------
__global__ __launch_bounds__(256) void decode_kernel(
    const float* __restrict__ props, const int* __restrict__ imidx,
    const float* __restrict__ imsizes, const float* __restrict__ reg_b)
{
    int idx = blockIdx.x * blockDim.x + threadIdx.x;
    if (idx >= NDET) return;
    int p = idx / NCLS, c = idx - p * NCLS;
    float4 pr = ((const float4*)props)[p];
    float pw = pr.z - pr.x, ph = pr.w - pr.y;
    float pcx = pr.x + 0.5f * pw, pcy = pr.y + 0.5f * ph;
    const float* r  = &g_headp[p * NHEAD + 128 + c * 4];
    const float* rb = &reg_b[c * 4];
    float dx = (r[0] + rb[0]) * 0.1f, dy = (r[1] + rb[1]) * 0.1f;
    float dw = fminf((r[2] + rb[2]) * 0.2f, BBOX_CLIP);
    float dh = fminf((r[3] + rb[3]) * 0.2f, BBOX_CLIP);
    float ncx = pcx + dx * pw, ncy = pcy + dy * ph;
    float nw = pw * expf(dw), nh = ph * expf(dh);
    int im = imidx[p];
    float hh = imsizes[im * 2 + 0], ww = imsizes[im * 2 + 1];
    float x1 = fminf(fmaxf(ncx - 0.5f * nw, 0.0f), ww);
    float y1 = fminf(fmaxf(ncy - 0.5f * nh, 0.0f), hh);
    float x2 = fminf(fmaxf(ncx + 0.5f * nw, 0.0f), ww);
    float y2 = fminf(fmaxf(ncy + 0.5f * nh, 0.0f), hh);
    float s = g_scr[idx];
    bool valid = (s > 0.05f) && (x2 - x1 > 0.0f) && (y2 - y1 > 0.0f);
    float sm = valid ? s : 0.0f;
    g_boxes[idx] = make_float4(x1, y1, x2, y2);
    g_keysA[idx] = ((u64)__float_as_uint(sm) << 32) | (u32)(~(u32)idx);
}

// -------------------------- bitonic sort machinery -------------------------
__device__ __forceinline__ void bitonic2048_desc(u64* s)
{
    const int t = threadIdx.x;
    for (int k = 2; k <= 2048; k <<= 1) {
        for (int j = k >> 1; j > 0; j >>= 1) {
            __syncthreads();
            int i   = ((t & ~(j - 1)) << 1) | (t & (j - 1));
            int ixj = i | j;
            bool dir = ((i & k) == 0);
            u64 a = s[i], b = s[ixj];
            if ((a < b) == dir) { s[i] = b; s[ixj] = a; }
        }
    }
    __syncthreads();
}

__global__ __launch_bounds__(1024) void local_sort_kernel(u64* __restrict__ keys)
{
    __shared__ u64 s[2048];
    const int base = blockIdx.x * 2048, t = threadIdx.x;
    s[t] = keys[base + t];
    s[t + 1024] = keys[base + t + 1024];
    bitonic2048_desc(s);
    keys[base + t] = s[t];
    keys[base + t + 1024] = s[t + 1024];
}

__device__ __forceinline__ void merge2_smem(u64* A, u64* Bv)
{
    const int t = threadIdx.x;
    __syncthreads();
    for (int e = t; e < 2048; e += 1024) {
        u64 x = A[e], y = Bv[2047 - e];
        A[e] = (x > y) ? x : y;
    }
    for (int j = 1024; j > 0; j >>= 1) {
        __syncthreads();
        int i   = ((t & ~(j - 1)) << 1) | (t & (j - 1));
        int ixj = i | j;
        u64 p = A[i], q = A[ixj];
        if (p < q) { A[i] = q; A[ixj] = p; }
    }
    __syncthreads();
}

__global__ __launch_bounds__(1024) void merge4_kernel(
    const u64* __restrict__ src, u64* __restrict__ dst, int nc)
{
    __shared__ u64 s0[2048];
    __shared__ u64 s1[2048];
    const int a = blockIdx.x, t = threadIdx.x;
    const int c0 = 4 * a;
    const int cnt = min(4, nc - c0);
    s0[t]        = src[c0 * 2048 + t];
    s0[t + 1024] = src[c0 * 2048 + t + 1024];
    for (int q = 1; q < cnt; q++) {
        s1[t]        = src[(c0 + q) * 2048 + t];
        s1[t + 1024] = src[(c0 + q) * 2048 + t + 1024];
        merge2_smem(s0, s1);
    }
    dst[a * 2048 + t]        = s0[t];
    dst[a * 2048 + t + 1024] = s0[t + 1024];
}

// ------------------------------ topk gather --------------------------------
__global__ __launch_bounds__(256) void gather_kernel(
    const u64* __restrict__ keys, const int* __restrict__ imidx)
{
    int r = blockIdx.x * blockDim.x + threadIdx.x;
    if (r >= KNMS) return;
    u64 key = keys[r];
    u32 idx = ~((u32)key);
    float s = __uint_as_float((u32)(key >> 32));
    float4 b = g_boxes[idx];
    int p = idx / NCLS, c = idx - p * NCLS;
    int im = imidx[p];
    float off = (float)(im * NCLS + c) * 100000.0f;
    g_ob[r] = make_float4(b.x + off, b.y + off, b.z + off, b.w + off);
    g_bk[r] = b;
    g_sk[r] = s;
    g_ck[r] = c;
    g_imk[r] = im;
    g_vk[r] = (s > 0.0f) ? 1 : 0;
}

// --------------------------------- NMS -------------------------------------
__global__ __launch_bounds__(64) void nms_mask_kernel()
{
    __shared__ float4 cb[64];
    const int t = threadIdx.x;
    const int c0 = blockIdx.x * 64;
    cb[t] = g_ob[c0 + t];
    __syncthreads();
    const int row = blockIdx.y * 64 + t;
    float4 rb = g_ob[row];
    float ra = (rb.z - rb.x) * (rb.w - rb.y);
    u64 bits = 0;
    #pragma unroll 4
    for (int j = 0; j < 64; j++) {
        float4 c = cb[j];
        float lx = fmaxf(rb.x, c.x), ly = fmaxf(rb.y, c.y);
        float rx = fminf(rb.z, c.z), ry = fminf(rb.w, c.w);
        float w = fmaxf(rx - lx, 0.0f), h = fmaxf(ry - ly, 0.0f);
        float inter = w * h;
        float ca = (c.z - c.x) * (c.w - c.y);
        float iou = inter / (ra + ca - inter + 1e-9f);
        if (iou > 0.5f) bits |= (1ULL << j);
    }
    g_mask[(size_t)row * 32 + blockIdx.x] = bits;
}

__global__ __launch_bounds__(32) void nms_scan_kernel()
{
    const int lane = threadIdx.x;
    u64 remv = 0;
    u64 cur[16], nxt[16];
    #pragma unroll
    for (int r = 0; r < 16; r++) cur[r] = g_mask[(size_t)r * 32 + lane];
    for (int c = 0; c < 128; c++) {
        if (c < 127) {
            #pragma unroll
            for (int r = 0; r < 16; r++)
                nxt[r] = g_mask[(size_t)((c + 1) * 16 + r) * 32 + lane];
        }
        u64 v0 = ((const u64*)g_vk)[c * 2];
        u64 v1 = ((const u64*)g_vk)[c * 2 + 1];
        #pragma unroll
        for (int r = 0; r < 16; r++) {
            int i = c * 16 + r;
            u64 w = __shfl_sync(0xffffffffu, remv, i >> 6);
            u64 vb = ((r < 8 ? (v0 >> (r * 8)) : (v1 >> ((r - 8) * 8))) & 1ULL);
            bool kept = vb && !((w >> (i & 63)) & 1ULL);
            if (kept) remv |= cur[r];
            if (lane == 0) g_keep[i] = kept ? 1 : 0;
        }
        #pragma unroll
        for (int r = 0; r < 16; r++) cur[r] = nxt[r];
    }
}

// -------------------------- per-image top-100 ------------------------------
__global__ __launch_bounds__(1024) void topk_image_kernel(float* __restrict__ out)
{
    __shared__ u64 s[2048];
    const int img = blockIdx.x, t = threadIdx.x;
    for (int e = t; e < 2048; e += 1024) {
        float val = (g_imk[e] == img) ? (g_keep[e] ? g_sk[e] : 0.0f) : -1.0f;
        u32 bits = __float_as_uint(val);
        u32 u = (bits & 0x80000000u) ? ~bits : (bits | 0x80000000u);
        s[e] = ((u64)u << 32) | (u32)(2047 - e);
    }
    bitonic2048_desc(s);
    if (t < 100) {
        u64 key = s[t];
        int r = 2047 - (int)(key & 0xFFFFFFFFu);
        u32 u = (u32)(key >> 32);
        float score = (u & 0x80000000u) ? __uint_as_float(u & 0x7FFFFFFFu) : 0.0f;
        float4 b = g_bk[r];
        out[(img * 100 + t) * 4 + 0] = b.x;
        out[(img * 100 + t) * 4 + 1] = b.y;
        out[(img * 100 + t) * 4 + 2] = b.z;
        out[(img * 100 + t) * 4 + 3] = b.w;
        out[1600 + img * 100 + t] = score;
        out[2000 + img * 100 + t] = (float)g_ck[r];
    }
}

// ------------------------------- launcher ----------------------------------
extern "C" void kernel_launch(void* const* d_in, const int* in_sizes, int n_in,
                              void* d_out, int out_size)
{
    const float* proposals = (const float*)d_in[0];
    const int*   imidx     = (const int*)d_in[1];
    const float* f0        = (const float*)d_in[2];
    const float* f1        = (const float*)d_in[3];
    const float* f2        = (const float*)d_in[4];
    const float* f3        = (const float*)d_in[5];
    const float* imsizes   = (const float*)d_in[6];
    const float* fc0_w     = (const float*)d_in[7];
    const float* fc0_b     = (const float*)d_in[8];
    const float* fc1_w     = (const float*)d_in[9];
    const float* fc1_b     = (const float*)d_in[10];
    const float* cls_w     = (const float*)d_in[11];
    const float* cls_b     = (const float*)d_in[12];
    const float* reg_w     = (const float*)d_in[13];
    const float* reg_b     = (const float*)d_in[14];
    float* out = (float*)d_out;

    void *pxh, *pxl, *pw0h, *pw0l, *pw1h, *pw1l, *pwHh, *pwHl;
    void *ppart, *ph1h, *ph1l, *ph2h, *ph2l, *pkA, *pkB;
    cudaGetSymbolAddress(&pxh,  g_xh);   cudaGetSymbolAddress(&pxl,  g_xl);
    cudaGetSymbolAddress(&pw0h, g_w0h);  cudaGetSymbolAddress(&pw0l, g_w0l);
    cudaGetSymbolAddress(&pw1h, g_w1h);  cudaGetSymbolAddress(&pw1l, g_w1l);
    cudaGetSymbolAddress(&pwHh, g_wHh);  cudaGetSymbolAddress(&pwHl, g_wHl);
    cudaGetSymbolAddress(&ppart, g_part);
    cudaGetSymbolAddress(&ph1h, g_h1h);  cudaGetSymbolAddress(&ph1l, g_h1l);
    cudaGetSymbolAddress(&ph2h, g_h2h);  cudaGetSymbolAddress(&ph2l, g_h2l);
    cudaGetSymbolAddress(&pkA,  g_keysA); cudaGetSymbolAddress(&pkB, g_keysB);

    cudaFuncSetAttribute(gemm_wmma_kernel, cudaFuncAttributeMaxDynamicSharedMemorySize, SMEM_GEMM);

    // 1-3. weight splits (independent of RoIAlign)
    split_pad_kernel<<<(CLIN * FEAT / 4 + 255) / 256, 256>>>(fc0_w, (__nv_bfloat16*)pw0h, (__nv_bfloat16*)pw0l, CLIN, FEAT, CLIN);
    split_pad_kernel<<<(CLIN * CLIN / 4 + 255) / 256, 256>>>(fc1_w, (__nv_bfloat16*)pw1h, (__nv_bfloat16*)pw1l, CLIN, CLIN, CLIN);
    split_pad_kernel<<<(128 * CLIN / 4 + 255) / 256, 256>>>(cls_w, (__nv_bfloat16*)pwHh, (__nv_bfloat16*)pwHl, 81, CLIN, 128);

    // 4. RoIAlign (launch #4 -> profiled by ncu this round)
    roi_align_kernel<<<P_PROP * 7, 256>>>(proposals, imidx, f0, f1, f2, f3);

    // 5. remaining head weight split (reg rows 128..511)
    split_pad_kernel<<<(384 * CLIN / 4 + 255) / 256, 256>>>(reg_w,
        (__nv_bfloat16*)pwHh + 128 * CLIN, (__nv_bfloat16*)pwHl + 128 * CLIN, 320, CLIN, 384);

    // 6. FC0: 128x128 tiles, BK=32, split-K=4
    gemm_wmma_kernel<<<dim3(8, 8, 4), 512, SMEM_GEMM>>>(
        (const __nv_bfloat16*)pxh, (const __nv_bfloat16*)pxl,
        (const __nv_bfloat16*)pw0h, (const __nv_bfloat16*)pw0l,
        (float*)ppart, CLIN, FEAT / 4, FEAT, P_PROP * CLIN);

    // 7. reduce 4 partials + bias + relu + split
    reduce_split_kernel<<<(P_PROP * CLIN / 4 + 255) / 256, 256>>>(
        (const float*)ppart, fc0_b, (__nv_bfloat16*)ph1h, (__nv_bfloat16*)ph1l, 4);

    // 8. FC1 split-K=4
    gemm_wmma_kernel<<<dim3(8, 8, 4), 512, SMEM_GEMM>>>(
        (const __nv_bfloat16*)ph1h, (const __nv_bfloat16*)ph1l,
        (const __nv_bfloat16*)pw1h, (const __nv_bfloat16*)pw1l,
        (float*)ppart, CLIN, CLIN / 4, CLIN, P_PROP * CLIN);

    // 9. reduce 4 partials + bias + relu + split
    reduce_split_kernel<<<(P_PROP * CLIN / 4 + 255) / 256, 256>>>(
        (const float*)ppart, fc1_b, (__nv_bfloat16*)ph2h, (__nv_bfloat16*)ph2l, 4);

    // 10. fused heads (N=512) split-K=4
    gemm_wmma_kernel<<<dim3(4, 8, 4), 512, SMEM_GEMM>>>(
        (const __nv_bfloat16*)ph2h, (const __nv_bfloat16*)ph2l,
        (const __nv_bfloat16*)pwHh, (const __nv_bfloat16*)pwHl,
        (float*)ppart, NHEAD, CLIN / 4, CLIN, P_PROP * NHEAD);

    // 11. head partial reduce (raw, bias fused downstream)
    head_reduce_kernel<<<(P_PROP * NHEAD / 4 + 255) / 256, 256>>>((const float*)ppart, 4);

    softmax_kernel<<<P_PROP, 128>>>(cls_b);
    decode_kernel<<<NDET / 256, 256>>>(proposals, imidx, imsizes, reg_b);

    // exact top-2048
    local_sort_kernel<<<40, 1024>>>((u64*)pkA);
    merge4_kernel<<<10, 1024>>>((const u64*)pkA, (u64*)pkB, 40);
    merge4_kernel<<<3, 1024>>>((const u64*)pkB, (u64*)pkA, 10);
    merge4_kernel<<<1, 1024>>>((const u64*)pkA, (u64*)pkB, 3);

    gather_kernel<<<KNMS / 256, 256>>>((const u64*)pkB, imidx);
    nms_mask_kernel<<<dim3(32, 32), 64>>>();
    nms_scan_kernel<<<1, 32>>>();
    topk_image_kernel<<<4, 1024>>>(out);
}

// round 17
// speedup vs baseline: 1.1297x; 1.1297x over previous
#include <cuda_runtime.h>
#include <cuda_bf16.h>
#include <mma.h>
#include <math.h>
#include <stdint.h>

using namespace nvcuda;

typedef unsigned long long u64;
typedef unsigned int u32;

#define P_PROP 1024
#define NCLS   80
#define NDET   (P_PROP * NCLS)   // 81920
#define KNMS   2048
#define FEAT   12544             // 256*7*7
#define CLIN   1024
#define NHEAD  512               // packed cls(128) + reg(384)
#define BBOX_CLIP 4.135166556742356f

// ------------------------- scratch (device globals; no runtime alloc) ------
__device__ __nv_bfloat16 g_xh [P_PROP * FEAT];
__device__ __nv_bfloat16 g_xl [P_PROP * FEAT];
__device__ __nv_bfloat16 g_w0h[CLIN * FEAT];
__device__ __nv_bfloat16 g_w0l[CLIN * FEAT];
__device__ __nv_bfloat16 g_w1h[CLIN * CLIN];
__device__ __nv_bfloat16 g_w1l[CLIN * CLIN];
__device__ __nv_bfloat16 g_wHh[NHEAD * CLIN];
__device__ __nv_bfloat16 g_wHl[NHEAD * CLIN];
__device__ float  g_part[4 * P_PROP * CLIN];     // split-K partials
__device__ __nv_bfloat16 g_h1h[P_PROP * CLIN];
__device__ __nv_bfloat16 g_h1l[P_PROP * CLIN];
__device__ __nv_bfloat16 g_h2h[P_PROP * CLIN];
__device__ __nv_bfloat16 g_h2l[P_PROP * CLIN];
__device__ float  g_headp[P_PROP * NHEAD];       // raw head out (no bias)
__device__ float  g_scr [P_PROP * NCLS];
__device__ float4 g_boxes[NDET];
__device__ u64    g_keysA[NDET];
__device__ u64    g_keysB[NDET / 2 + 4096];
__device__ float4 g_bk  [KNMS];
__device__ float4 g_ob  [KNMS];
__device__ float  g_sk  [KNMS];
__device__ int    g_ck  [KNMS];
__device__ int    g_imk [KNMS];
__device__ unsigned char g_vk  [KNMS];
__device__ unsigned char g_keep[KNMS];
__device__ u64    g_mask[KNMS * 32];

__device__ __forceinline__ unsigned short bfbits(float x) {
    __nv_bfloat16 b = __float2bfloat16(x);
    return *(unsigned short*)&b;
}

// --------------------------------- RoIAlign --------------------------------
// block = (proposal, output row); warps stride channels, 4 channels in flight.
__global__ __launch_bounds__(256) void roi_align_kernel(
    const float* __restrict__ props, const int* __restrict__ imidx,
    const float* __restrict__ f0, const float* __restrict__ f1,
    const float* __restrict__ f2, const float* __restrict__ f3)
{
    const int p  = blockIdx.x / 7;
    const int oy = blockIdx.x % 7;

    __shared__ int   s_xc[28];
    __shared__ float s_xw[28];
    __shared__ int   s_yr[4];
    __shared__ float s_yw[4];
    __shared__ int   s_l, s_im, s_H, s_W;

    if (threadIdx.x < 32) {
        float4 pr = ((const float4*)props)[p];
        float w = pr.z - pr.x, h = pr.w - pr.y;
        float t = sqrtf(w * h) / 224.0f + 1e-8f;
        float lv = floorf(4.0f + log2f(t));
        int l = (int)fminf(fmaxf(lv, 2.0f), 5.0f) - 2;
        int H = 160 >> l, W = 160 >> l;
        float inv = 1.0f / (float)(4 << l);
        float x1 = pr.x * inv - 0.5f, x2 = pr.z * inv - 0.5f;
        float y1 = pr.y * inv - 0.5f, y2 = pr.w * inv - 0.5f;
        float bw = (x2 - x1) / 7.0f, bh = (y2 - y1) / 7.0f;
        int lane = threadIdx.x;
        if (lane < 28) {
            int j = lane >> 1;
            float g  = ((float)j + 0.5f) * 0.5f;
            float xs = x1 + bw * g;
            float vx = (xs > -1.0f && xs < (float)W) ? 1.0f : 0.0f;
            float v  = fminf(fmaxf(xs, 0.0f), (float)W - 1.0f);
            float lo = floorf(v);
            int loi = (int)lo;
            int hii = min(loi + 1, W - 1);
            float fx = v - lo;
            s_xc[lane] = (lane & 1) ? hii : loi;
            s_xw[lane] = (lane & 1) ? (fx * vx) : ((1.0f - fx) * vx);
        }
        if (lane < 4) {
            int q = lane >> 1;
            int sy = oy * 2 + q;
            float g  = ((float)sy + 0.5f) * 0.5f;
            float ys = y1 + bh * g;
            float vy = (ys > -1.0f && ys < (float)H) ? 1.0f : 0.0f;
            float v  = fminf(fmaxf(ys, 0.0f), (float)H - 1.0f);
            float lo = floorf(v);
            int loi = (int)lo;
            int hii = min(loi + 1, H - 1);
            float fy = v - lo;
            s_yr[lane] = (lane & 1) ? hii : loi;
            s_yw[lane] = (lane & 1) ? (fy * vy) : ((1.0f - fy) * vy);
        }
        if (lane == 0) { s_l = l; s_im = imidx[p]; s_H = H; s_W = W; }
    }
    __syncthreads();

    const int l = s_l, H = s_H, W = s_W, im = s_im;
    const float* fm = (l == 0) ? f0 : (l == 1) ? f1 : (l == 2) ? f2 : f3;
    const size_t HW = (size_t)H * W;
    const float* base_im = fm + (size_t)im * 256 * HW;

    const int warp = threadIdx.x >> 5;
    const int lane = threadIdx.x & 31;
    const float xw = (lane < 28) ? s_xw[lane] : 0.0f;
    const int   xc = (lane < 28) ? s_xc[lane] : 0;
    const float w0 = s_yw[0], w1 = s_yw[1], w2 = s_yw[2], w3 = s_yw[3];
    // loop-invariant row offsets
    const int o0 = s_yr[0] * W + xc;
    const int o1 = s_yr[1] * W + xc;
    const int o2 = s_yr[2] * W + xc;
    const int o3 = s_yr[3] * W + xc;
    const bool wr = (lane < 28) && ((lane & 3) == 0);
    const size_t obase = (size_t)p * FEAT + oy * 7 + (lane >> 2);

    #pragma unroll 1
    for (int it = 0; it < 8; it++) {
        const int cb = warp + it * 32;
        const float* bu = base_im + (size_t)cb * HW;
        float acc[4];
        #pragma unroll
        for (int u = 0; u < 4; u++) {
            const float* bc = bu + (size_t)(u * 8) * HW;
            acc[u] = (w0 * bc[o0] + w1 * bc[o1] + w2 * bc[o2] + w3 * bc[o3]) * xw;
        }
        #pragma unroll
        for (int u = 0; u < 4; u++) {
            float m = acc[u];
            m += __shfl_xor_sync(0xffffffffu, m, 1);
            m += __shfl_xor_sync(0xffffffffu, m, 2);
            if (wr) {
                float val = m * 0.25f;
                size_t off = obase + (size_t)(cb + u * 8) * 49;
                __nv_bfloat16 hi = __float2bfloat16(val);
                g_xh[off] = hi;
                g_xl[off] = __float2bfloat16(val - __bfloat162float(hi));
            }
        }
    }
}

// ------------- fp32 -> bf16 hi/lo split (weights, row-pad, x4 vec) ---------
__global__ __launch_bounds__(256) void split_pad_kernel(
    const float* __restrict__ src, __nv_bfloat16* __restrict__ hi,
    __nv_bfloat16* __restrict__ lo, int rows, int K, int prows)
{
    int i4 = blockIdx.x * 256 + threadIdx.x;
    int total4 = (prows * K) >> 2;
    if (i4 >= total4) return;
    int i = i4 << 2;
    int r = i / K;
    float4 x = make_float4(0.f, 0.f, 0.f, 0.f);
    if (r < rows) x = *(const float4*)(src + i);
    ushort4 h4, l4;
    h4.x = bfbits(x.x); l4.x = bfbits(x.x - __bfloat162float(__float2bfloat16(x.x)));
    h4.y = bfbits(x.y); l4.y = bfbits(x.y - __bfloat162float(__float2bfloat16(x.y)));
    h4.z = bfbits(x.z); l4.z = bfbits(x.z - __bfloat162float(__float2bfloat16(x.z)));
    h4.w = bfbits(x.w); l4.w = bfbits(x.w - __bfloat162float(__float2bfloat16(x.w)));
    *(ushort4*)((unsigned short*)hi + i) = h4;
    *(ushort4*)((unsigned short*)lo + i) = l4;
}

// ---------- partial reduce (cnt buffers) + bias + relu + bf16 split --------
__global__ __launch_bounds__(256) void reduce_split_kernel(
    const float* __restrict__ P, const float* __restrict__ bias,
    __nv_bfloat16* __restrict__ hi, __nv_bfloat16* __restrict__ lo, int cnt)
{
    int i4 = blockIdx.x * 256 + threadIdx.x;
    if (i4 >= (P_PROP * CLIN) >> 2) return;
    int i = i4 << 2;
    float4 a = *(const float4*)(P + i);
    for (int q = 1; q < cnt; q++) {
        float4 b = *(const float4*)(P + (size_t)q * P_PROP * CLIN + i);
        a.x += b.x; a.y += b.y; a.z += b.z; a.w += b.w;
    }
    float4 bb = *(const float4*)(bias + (i & (CLIN - 1)));
    float v0 = fmaxf(a.x + bb.x, 0.f);
    float v1 = fmaxf(a.y + bb.y, 0.f);
    float v2 = fmaxf(a.z + bb.z, 0.f);
    float v3 = fmaxf(a.w + bb.w, 0.f);
    ushort4 h4, l4;
    h4.x = bfbits(v0); l4.x = bfbits(v0 - __bfloat162float(__float2bfloat16(v0)));
    h4.y = bfbits(v1); l4.y = bfbits(v1 - __bfloat162float(__float2bfloat16(v1)));
    h4.z = bfbits(v2); l4.z = bfbits(v2 - __bfloat162float(__float2bfloat16(v2)));
    h4.w = bfbits(v3); l4.w = bfbits(v3 - __bfloat162float(__float2bfloat16(v3)));
    *(ushort4*)((unsigned short*)hi + i) = h4;
    *(ushort4*)((unsigned short*)lo + i) = l4;
}

// ------------------- head partial reduce (cnt buffers, raw) ----------------
__global__ __launch_bounds__(256) void head_reduce_kernel(const float* __restrict__ P, int cnt)
{
    int i4 = blockIdx.x * 256 + threadIdx.x;
    if (i4 >= (P_PROP * NHEAD) >> 2) return;
    int i = i4 << 2;
    float4 a = *(const float4*)(P + i);
    for (int q = 1; q < cnt; q++) {
        float4 b = *(const float4*)(P + (size_t)q * P_PROP * NHEAD + i);
        a.x += b.x; a.y += b.y; a.z += b.z; a.w += b.w;
    }
    *(float4*)(g_headp + i) = a;
}

// -------------------------- wmma split-bf16 GEMM (R12-proven) --------------
#define LDT 40                       // smem row pitch (elements)
#define MATE (128 * LDT)             // elements per matrix tile (5120)
#define STAGEE (4 * MATE)            // elements per stage (20480)
#define NSTAGE 4
#define SMEM_GEMM (NSTAGE * STAGEE * 2)   // bytes (163840)

__global__ __launch_bounds__(512) void gemm_wmma_kernel(
    const __nv_bfloat16* __restrict__ Ah, const __nv_bfloat16* __restrict__ Al,
    const __nv_bfloat16* __restrict__ Bh, const __nv_bfloat16* __restrict__ Bl,
    float* __restrict__ C, int N, int K, int ldk, int partStride)
{
    extern __shared__ __align__(32) __nv_bfloat16 smem[];
    const int tid = threadIdx.x;
    const int wid = tid >> 5;
    const int wm = wid & 3;
    const int wn = wid >> 2;
    const size_t arow = (size_t)blockIdx.y * 128;
    const size_t brow = (size_t)blockIdx.x * 128;
    const size_t koff = (size_t)blockIdx.z * K;

    const int row = tid >> 2;
    const int seg = tid & 3;

    wmma::fragment<wmma::accumulator, 16, 16, 16, float> cf[2][2];
    #pragma unroll
    for (int i = 0; i < 2; i++)
        #pragma unroll
        for (int j = 0; j < 2; j++) wmma::fill_fragment(cf[i][j], 0.0f);

    uint4 rAh, rAl, rBh, rBl;
    auto reg_load = [&](size_t kpos) {
        size_t ga = (arow + row) * (size_t)ldk + kpos + seg * 8;
        size_t gb = (brow + row) * (size_t)ldk + kpos + seg * 8;
        rAh = *(const uint4*)(Ah + ga);
        rAl = *(const uint4*)(Al + ga);
        rBh = *(const uint4*)(Bh + gb);
        rBl = *(const uint4*)(Bl + gb);
    };
    auto smem_store = [&](int st) {
        __nv_bfloat16* base = smem + st * STAGEE;
        int so = row * LDT + seg * 8;
        *(uint4*)(base + so)            = rAh;
        *(uint4*)(base + MATE + so)     = rAl;
        *(uint4*)(base + 2 * MATE + so) = rBh;
        *(uint4*)(base + 3 * MATE + so) = rBl;
    };

    const int nch = K / 32;
    reg_load(koff);
    smem_store(0);
    if (nch > 1) {
        reg_load(koff + 32);
        smem_store(1);
    }
    __syncthreads();

    for (int ch = 0; ch < nch; ch++) {
        const bool pf = (ch + 2 < nch);
        if (pf) reg_load(koff + (size_t)(ch + 2) * 32);
        {
            const __nv_bfloat16* base = smem + (ch & (NSTAGE - 1)) * STAGEE;
            const __nv_bfloat16* sAh = base;
            const __nv_bfloat16* sAl = base + MATE;
            const __nv_bfloat16* sBh = base + 2 * MATE;
            const __nv_bfloat16* sBl = base + 3 * MATE;
            #pragma unroll
            for (int ks = 0; ks < 2; ks++) {
                wmma::fragment<wmma::matrix_a, 16, 16, 16, __nv_bfloat16, wmma::row_major> ah[2], al[2];
                wmma::fragment<wmma::matrix_b, 16, 16, 16, __nv_bfloat16, wmma::col_major> bh[2], bl[2];
                #pragma unroll
                for (int i = 0; i < 2; i++) {
                    wmma::load_matrix_sync(ah[i], sAh + (wm * 32 + i * 16) * LDT + ks * 16, LDT);
                    wmma::load_matrix_sync(al[i], sAl + (wm * 32 + i * 16) * LDT + ks * 16, LDT);
                }
                #pragma unroll
                for (int j = 0; j < 2; j++) {
                    wmma::load_matrix_sync(bh[j], sBh + (wn * 32 + j * 16) * LDT + ks * 16, LDT);
                    wmma::load_matrix_sync(bl[j], sBl + (wn * 32 + j * 16) * LDT + ks * 16, LDT);
                }
                #pragma unroll
                for (int i = 0; i < 2; i++)
                    #pragma unroll
                    for (int j = 0; j < 2; j++) {
                        wmma::mma_sync(cf[i][j], ah[i], bh[j], cf[i][j]);
                        wmma::mma_sync(cf[i][j], ah[i], bl[j], cf[i][j]);
                        wmma::mma_sync(cf[i][j], al[i], bh[j], cf[i][j]);
                    }
            }
        }
        __syncthreads();
        if (pf) smem_store((ch + 2) & (NSTAGE - 1));
    }

    float* Cout = C + (size_t)blockIdx.z * partStride;
    #pragma unroll
    for (int i = 0; i < 2; i++)
        #pragma unroll
        for (int j = 0; j < 2; j++)
            wmma::store_matrix_sync(
                Cout + (arow + wm * 32 + i * 16) * (size_t)N + brow + wn * 32 + j * 16,
                cf[i][j], N, wmma::mem_row_major);
}

// --------------------------------- softmax ---------------------------------
__global__ __launch_bounds__(128) void softmax_kernel(const float* __restrict__ cls_b)
{
    const int p = blockIdx.x, t = threadIdx.x;
    __shared__ float red[128];
    float v = (t < 81) ? (g_headp[p * NHEAD + t] + cls_b[t]) : -3.0e38f;
    red[t] = v; __syncthreads();
    for (int s = 64; s > 0; s >>= 1) {
        if (t < s) red[t] = fmaxf(red[t], red[t + s]);
        __syncthreads();
    }
    float mx = red[0]; __syncthreads();
    float e = (t < 81) ? expf(v - mx) : 0.0f;
    red[t] = e; __syncthreads();
    for (int s = 64; s > 0; s >>= 1) {
        if (t < s) red[t] += red[t + s];
        __syncthreads();
    }
    float total = red[0];
    if (t < 80) g_scr[p * NCLS + t] = e / total;
}

// ------------------------------- box decode --------------------------------
__global__ __launch_bounds__(256) void decode_kernel(
    const float* __restrict__ props, const int* __restrict__ imidx,
    const float* __restrict__ imsizes, const float* __restrict__ reg_b)
{
    int idx = blockIdx.x * blockDim.x + threadIdx.x;
    if (idx >= NDET) return;
    int p = idx / NCLS, c = idx - p * NCLS;
    float4 pr = ((const float4*)props)[p];
    float pw = pr.z - pr.x, ph = pr.w - pr.y;
    float pcx = pr.x + 0.5f * pw, pcy = pr.y + 0.5f * ph;
    const float* r  = &g_headp[p * NHEAD + 128 + c * 4];
    const float* rb = &reg_b[c * 4];
    float dx = (r[0] + rb[0]) * 0.1f, dy = (r[1] + rb[1]) * 0.1f;
    float dw = fminf((r[2] + rb[2]) * 0.2f, BBOX_CLIP);
    float dh = fminf((r[3] + rb[3]) * 0.2f, BBOX_CLIP);
    float ncx = pcx + dx * pw, ncy = pcy + dy * ph;
    float nw = pw * expf(dw), nh = ph * expf(dh);
    int im = imidx[p];
    float hh = imsizes[im * 2 + 0], ww = imsizes[im * 2 + 1];
    float x1 = fminf(fmaxf(ncx - 0.5f * nw, 0.0f), ww);
    float y1 = fminf(fmaxf(ncy - 0.5f * nh, 0.0f), hh);
    float x2 = fminf(fmaxf(ncx + 0.5f * nw, 0.0f), ww);
    float y2 = fminf(fmaxf(ncy + 0.5f * nh, 0.0f), hh);
    float s = g_scr[idx];
    bool valid = (s > 0.05f) && (x2 - x1 > 0.0f) && (y2 - y1 > 0.0f);
    float sm = valid ? s : 0.0f;
    g_boxes[idx] = make_float4(x1, y1, x2, y2);
    g_keysA[idx] = ((u64)__float_as_uint(sm) << 32) | (u32)(~(u32)idx);
}

// -------------------------- bitonic sort machinery (R15-proven) ------------
__device__ __forceinline__ void bitonic2048_desc(u64* s)
{
    const int t = threadIdx.x;
    for (int k = 2; k <= 2048; k <<= 1) {
        for (int j = k >> 1; j > 0; j >>= 1) {
            __syncthreads();
            int i   = ((t & ~(j - 1)) << 1) | (t & (j - 1));
            int ixj = i | j;
            bool dir = ((i & k) == 0);
            u64 a = s[i], b = s[ixj];
            if ((a < b) == dir) { s[i] = b; s[ixj] = a; }
        }
    }
    __syncthreads();
}

__global__ __launch_bounds__(1024) void local_sort_kernel(u64* __restrict__ keys)
{
    __shared__ u64 s[2048];
    const int base = blockIdx.x * 2048, t = threadIdx.x;
    s[t] = keys[base + t];
    s[t + 1024] = keys[base + t + 1024];
    bitonic2048_desc(s);
    keys[base + t] = s[t];
    keys[base + t + 1024] = s[t + 1024];
}

__device__ __forceinline__ void merge2_smem(u64* A, u64* Bv)
{
    const int t = threadIdx.x;
    __syncthreads();
    for (int e = t; e < 2048; e += 1024) {
        u64 x = A[e], y = Bv[2047 - e];
        A[e] = (x > y) ? x : y;
    }
    for (int j = 1024; j > 0; j >>= 1) {
        __syncthreads();
        int i   = ((t & ~(j - 1)) << 1) | (t & (j - 1));
        int ixj = i | j;
        u64 p = A[i], q = A[ixj];
        if (p < q) { A[i] = q; A[ixj] = p; }
    }
    __syncthreads();
}

__global__ __launch_bounds__(1024) void merge4_kernel(
    const u64* __restrict__ src, u64* __restrict__ dst, int nc)
{
    __shared__ u64 s0[2048];
    __shared__ u64 s1[2048];
    const int a = blockIdx.x, t = threadIdx.x;
    const int c0 = 4 * a;
    const int cnt = min(4, nc - c0);
    s0[t]        = src[c0 * 2048 + t];
    s0[t + 1024] = src[c0 * 2048 + t + 1024];
    for (int q = 1; q < cnt; q++) {
        s1[t]        = src[(c0 + q) * 2048 + t];
        s1[t + 1024] = src[(c0 + q) * 2048 + t + 1024];
        merge2_smem(s0, s1);
    }
    dst[a * 2048 + t]        = s0[t];
    dst[a * 2048 + t + 1024] = s0[t + 1024];
}

// ------------------------------ topk gather --------------------------------
__global__ __launch_bounds__(256) void gather_kernel(
    const u64* __restrict__ keys, const int* __restrict__ imidx)
{
    int r = blockIdx.x * blockDim.x + threadIdx.x;
    if (r >= KNMS) return;
    u64 key = keys[r];
    u32 idx = ~((u32)key);
    float s = __uint_as_float((u32)(key >> 32));
    float4 b = g_boxes[idx];
    int p = idx / NCLS, c = idx - p * NCLS;
    int im = imidx[p];
    float off = (float)(im * NCLS + c) * 100000.0f;
    g_ob[r] = make_float4(b.x + off, b.y + off, b.z + off, b.w + off);
    g_bk[r] = b;
    g_sk[r] = s;
    g_ck[r] = c;
    g_imk[r] = im;
    g_vk[r] = (s > 0.0f) ? 1 : 0;
}

// --------------------------------- NMS -------------------------------------
__global__ __launch_bounds__(64) void nms_mask_kernel()
{
    __shared__ float4 cb[64];
    const int t = threadIdx.x;
    const int c0 = blockIdx.x * 64;
    cb[t] = g_ob[c0 + t];
    __syncthreads();
    const int row = blockIdx.y * 64 + t;
    float4 rb = g_ob[row];
    float ra = (rb.z - rb.x) * (rb.w - rb.y);
    u64 bits = 0;
    #pragma unroll 4
    for (int j = 0; j < 64; j++) {
        float4 c = cb[j];
        float lx = fmaxf(rb.x, c.x), ly = fmaxf(rb.y, c.y);
        float rx = fminf(rb.z, c.z), ry = fminf(rb.w, c.w);
        float w = fmaxf(rx - lx, 0.0f), h = fmaxf(ry - ly, 0.0f);
        float inter = w * h;
        float ca = (c.z - c.x) * (c.w - c.y);
        float iou = inter / (ra + ca - inter + 1e-9f);
        if (iou > 0.5f) bits |= (1ULL << j);
    }
    g_mask[(size_t)row * 32 + blockIdx.x] = bits;
}

__global__ __launch_bounds__(32) void nms_scan_kernel()
{
    const int lane = threadIdx.x;
    u64 remv = 0;
    u64 cur[16], nxt[16];
    #pragma unroll
    for (int r = 0; r < 16; r++) cur[r] = g_mask[(size_t)r * 32 + lane];
    for (int c = 0; c < 128; c++) {
        if (c < 127) {
            #pragma unroll
            for (int r = 0; r < 16; r++)
                nxt[r] = g_mask[(size_t)((c + 1) * 16 + r) * 32 + lane];
        }
        u64 v0 = ((const u64*)g_vk)[c * 2];
        u64 v1 = ((const u64*)g_vk)[c * 2 + 1];
        #pragma unroll
        for (int r = 0; r < 16; r++) {
            int i = c * 16 + r;
            u64 w = __shfl_sync(0xffffffffu, remv, i >> 6);
            u64 vb = ((r < 8 ? (v0 >> (r * 8)) : (v1 >> ((r - 8) * 8))) & 1ULL);
            bool kept = vb && !((w >> (i & 63)) & 1ULL);
            if (kept) remv |= cur[r];
            if (lane == 0) g_keep[i] = kept ? 1 : 0;
        }
        #pragma unroll
        for (int r = 0; r < 16; r++) cur[r] = nxt[r];
    }
}

// -------------------------- per-image top-100 ------------------------------
__global__ __launch_bounds__(1024) void topk_image_kernel(float* __restrict__ out)
{
    __shared__ u64 s[2048];
    const int img = blockIdx.x, t = threadIdx.x;
    for (int e = t; e < 2048; e += 1024) {
        float val = (g_imk[e] == img) ? (g_keep[e] ? g_sk[e] : 0.0f) : -1.0f;
        u32 bits = __float_as_uint(val);
        u32 u = (bits & 0x80000000u) ? ~bits : (bits | 0x80000000u);
        s[e] = ((u64)u << 32) | (u32)(2047 - e);
    }
    bitonic2048_desc(s);
    if (t < 100) {
        u64 key = s[t];
        int r = 2047 - (int)(key & 0xFFFFFFFFu);
        u32 u = (u32)(key >> 32);
        float score = (u & 0x80000000u) ? __uint_as_float(u & 0x7FFFFFFFu) : 0.0f;
        float4 b = g_bk[r];
        out[(img * 100 + t) * 4 + 0] = b.x;
        out[(img * 100 + t) * 4 + 1] = b.y;
        out[(img * 100 + t) * 4 + 2] = b.z;
        out[(img * 100 + t) * 4 + 3] = b.w;
        out[1600 + img * 100 + t] = score;
        out[2000 + img * 100 + t] = (float)g_ck[r];
    }
}

// ------------------------------- launcher ----------------------------------
extern "C" void kernel_launch(void* const* d_in, const int* in_sizes, int n_in,
                              void* d_out, int out_size)
{
    const float* proposals = (const float*)d_in[0];
    const int*   imidx     = (const int*)d_in[1];
    const float* f0        = (const float*)d_in[2];
    const float* f1        = (const float*)d_in[3];
    const float* f2        = (const float*)d_in[4];
    const float* f3        = (const float*)d_in[5];
    const float* imsizes   = (const float*)d_in[6];
    const float* fc0_w     = (const float*)d_in[7];
    const float* fc0_b     = (const float*)d_in[8];
    const float* fc1_w     = (const float*)d_in[9];
    const float* fc1_b     = (const float*)d_in[10];
    const float* cls_w     = (const float*)d_in[11];
    const float* cls_b     = (const float*)d_in[12];
    const float* reg_w     = (const float*)d_in[13];
    const float* reg_b     = (const float*)d_in[14];
    float* out = (float*)d_out;

    void *pxh, *pxl, *pw0h, *pw0l, *pw1h, *pw1l, *pwHh, *pwHl;
    void *ppart, *ph1h, *ph1l, *ph2h, *ph2l, *pkA, *pkB;
    cudaGetSymbolAddress(&pxh,  g_xh);   cudaGetSymbolAddress(&pxl,  g_xl);
    cudaGetSymbolAddress(&pw0h, g_w0h);  cudaGetSymbolAddress(&pw0l, g_w0l);
    cudaGetSymbolAddress(&pw1h, g_w1h);  cudaGetSymbolAddress(&pw1l, g_w1l);
    cudaGetSymbolAddress(&pwHh, g_wHh);  cudaGetSymbolAddress(&pwHl, g_wHl);
    cudaGetSymbolAddress(&ppart, g_part);
    cudaGetSymbolAddress(&ph1h, g_h1h);  cudaGetSymbolAddress(&ph1l, g_h1l);
    cudaGetSymbolAddress(&ph2h, g_h2h);  cudaGetSymbolAddress(&ph2l, g_h2l);
    cudaGetSymbolAddress(&pkA,  g_keysA); cudaGetSymbolAddress(&pkB, g_keysB);

    cudaFuncSetAttribute(gemm_wmma_kernel, cudaFuncAttributeMaxDynamicSharedMemorySize, SMEM_GEMM);

    // 1-3. weight splits (independent of RoIAlign)
    split_pad_kernel<<<(CLIN * FEAT / 4 + 255) / 256, 256>>>(fc0_w, (__nv_bfloat16*)pw0h, (__nv_bfloat16*)pw0l, CLIN, FEAT, CLIN);
    split_pad_kernel<<<(CLIN * CLIN / 4 + 255) / 256, 256>>>(fc1_w, (__nv_bfloat16*)pw1h, (__nv_bfloat16*)pw1l, CLIN, CLIN, CLIN);
    split_pad_kernel<<<(128 * CLIN / 4 + 255) / 256, 256>>>(cls_w, (__nv_bfloat16*)pwHh, (__nv_bfloat16*)pwHl, 81, CLIN, 128);

    // 4. RoIAlign (launch #4 -> profiled by ncu)
    roi_align_kernel<<<P_PROP * 7, 256>>>(proposals, imidx, f0, f1, f2, f3);

    // 5. remaining head weight split (reg rows 128..511)
    split_pad_kernel<<<(384 * CLIN / 4 + 255) / 256, 256>>>(reg_w,
        (__nv_bfloat16*)pwHh + 128 * CLIN, (__nv_bfloat16*)pwHl + 128 * CLIN, 320, CLIN, 384);

    // 6. FC0: 128x128 tiles, BK=32, split-K=4
    gemm_wmma_kernel<<<dim3(8, 8, 4), 512, SMEM_GEMM>>>(
        (const __nv_bfloat16*)pxh, (const __nv_bfloat16*)pxl,
        (const __nv_bfloat16*)pw0h, (const __nv_bfloat16*)pw0l,
        (float*)ppart, CLIN, FEAT / 4, FEAT, P_PROP * CLIN);

    // 7. reduce 4 partials + bias + relu + split
    reduce_split_kernel<<<(P_PROP * CLIN / 4 + 255) / 256, 256>>>(
        (const float*)ppart, fc0_b, (__nv_bfloat16*)ph1h, (__nv_bfloat16*)ph1l, 4);

    // 8. FC1 split-K=4
    gemm_wmma_kernel<<<dim3(8, 8, 4), 512, SMEM_GEMM>>>(
        (const __nv_bfloat16*)ph1h, (const __nv_bfloat16*)ph1l,
        (const __nv_bfloat16*)pw1h, (const __nv_bfloat16*)pw1l,
        (float*)ppart, CLIN, CLIN / 4, CLIN, P_PROP * CLIN);

    // 9. reduce 4 partials + bias + relu + split
    reduce_split_kernel<<<(P_PROP * CLIN / 4 + 255) / 256, 256>>>(
        (const float*)ppart, fc1_b, (__nv_bfloat16*)ph2h, (__nv_bfloat16*)ph2l, 4);

    // 10. fused heads (N=512) split-K=4
    gemm_wmma_kernel<<<dim3(4, 8, 4), 512, SMEM_GEMM>>>(
        (const __nv_bfloat16*)ph2h, (const __nv_bfloat16*)ph2l,
        (const __nv_bfloat16*)pwHh, (const __nv_bfloat16*)pwHl,
        (float*)ppart, NHEAD, CLIN / 4, CLIN, P_PROP * NHEAD);

    // 11. head partial reduce (raw, bias fused downstream)
    head_reduce_kernel<<<(P_PROP * NHEAD / 4 + 255) / 256, 256>>>((const float*)ppart, 4);

    softmax_kernel<<<P_PROP, 128>>>(cls_b);
    decode_kernel<<<NDET / 256, 256>>>(proposals, imidx, imsizes, reg_b);

    // exact top-2048
    local_sort_kernel<<<40, 1024>>>((u64*)pkA);
    merge4_kernel<<<10, 1024>>>((const u64*)pkA, (u64*)pkB, 40);
    merge4_kernel<<<3, 1024>>>((const u64*)pkB, (u64*)pkA, 10);
    merge4_kernel<<<1, 1024>>>((const u64*)pkA, (u64*)pkB, 3);

    gather_kernel<<<KNMS / 256, 256>>>((const u64*)pkB, imidx);
    nms_mask_kernel<<<dim3(32, 32), 64>>>();
    nms_scan_kernel<<<1, 32>>>();
    topk_image_kernel<<<4, 1024>>>(out);
}